// round 10
// baseline (speedup 1.0000x reference)
#include <cuda_runtime.h>
#include <cstdint>

#define BB 64
#define TT 2048
#define VV 256
#define HH 64
#define NHH 4
#define HDD 16
#define NLVL 2
#define G4H 256
#define NROWS (BB * TT)   // 131072

#define LP 68             // padded smem row (floats): bank shift 4/row

typedef unsigned long long ull;

// ---------------- scratch ----------------
__device__ float g_table[VV * G4H];             // 256 KB
__device__ float g_bufA[(size_t)NROWS * HH];    // 32 MB
__device__ float g_bufB[(size_t)NROWS * HH];    // 32 MB
__device__ float g_qkv[(size_t)NROWS * 3 * HH]; // 96 MB
__device__ float g_att[(size_t)NROWS * HH];     // 32 MB

// tf32 hi/lo weight scratch: [qkv 2*192*64 | wo 2*64*64 | fc 256*64]
#define WQKV_OFF 0
#define WO_OFF   24576
#define WFC_OFF  32768
#define WTOT     49152
__device__ unsigned g_whi[WTOT];
__device__ unsigned g_wlo[WTOT];

// ---------------- packed f32x2 helpers ----------------
__device__ __forceinline__ ull fma2(ull a, ull b, ull c) {
    ull d; asm("fma.rn.f32x2 %0,%1,%2,%3;" : "=l"(d) : "l"(a), "l"(b), "l"(c)); return d;
}
__device__ __forceinline__ ull add2(ull a, ull b) {
    ull d; asm("add.rn.f32x2 %0,%1,%2;" : "=l"(d) : "l"(a), "l"(b)); return d;
}
__device__ __forceinline__ float hadd2(ull a) {
    float lo, hi; asm("mov.b64 {%0,%1},%2;" : "=f"(lo), "=f"(hi) : "l"(a)); return lo + hi;
}
__device__ __forceinline__ ull dup2(float x) {
    ull d; asm("mov.b64 %0,{%1,%1};" : "=l"(d) : "f"(x)); return d;
}
__device__ __forceinline__ float2 unpk2(ull a) {
    float2 r; asm("mov.b64 {%0,%1},%2;" : "=f"(r.x), "=f"(r.y) : "l"(a)); return r;
}
__device__ __forceinline__ float htanh(float x) {
    float r; asm("tanh.approx.f32 %0,%1;" : "=f"(r) : "f"(x)); return r;
}

// ---------------- tf32 helpers ----------------
__device__ __forceinline__ unsigned f2tf(float a) {
    unsigned r; asm("cvt.rna.tf32.f32 %0,%1;" : "=r"(r) : "f"(a)); return r;
}
__device__ __forceinline__ void mma_tf32(
    float& c0, float& c1, float& c2, float& c3,
    unsigned a0, unsigned a1, unsigned a2, unsigned a3,
    unsigned b0, unsigned b1)
{
    asm("mma.sync.aligned.m16n8k8.row.col.f32.tf32.tf32.f32 "
        "{%0,%1,%2,%3},{%4,%5,%6,%7},{%8,%9},{%0,%1,%2,%3};"
        : "+f"(c0), "+f"(c1), "+f"(c2), "+f"(c3)
        : "r"(a0), "r"(a1), "r"(a2), "r"(a3), "r"(b0), "r"(b1));
}

// ---------------- 0) split all weights into tf32 hi/lo ----------------
__global__ void __launch_bounds__(256) wsplit_kernel(
    const float* __restrict__ wqkv, const float* __restrict__ wo,
    const float* __restrict__ fcw)
{
    int idx = blockIdx.x * 256 + threadIdx.x;
    if (idx >= WTOT) return;
    float v;
    if (idx < WO_OFF)       v = wqkv[idx];
    else if (idx < WFC_OFF) v = wo[idx - WO_OFF];
    else                    v = fcw[idx - WFC_OFF];
    unsigned hi = f2tf(v);
    float lo = v - __uint_as_float(hi);
    g_whi[idx] = hi;
    g_wlo[idx] = f2tf(lo);
}

// ---------------- 1) vocab -> gate-preact table ----------------
__global__ void __launch_bounds__(G4H) table_kernel(
    const float* __restrict__ emb, const float* __restrict__ w_ih,
    const float* __restrict__ b_ih, const float* __restrict__ b_hh)
{
    __shared__ __align__(16) float e[HH];
    const int v = blockIdx.x;
    const int j = threadIdx.x;
    if (j < HH) e[j] = emb[v * HH + j];
    __syncthreads();
    float acc = b_ih[j] + b_hh[j];
    const float* wr = w_ih + j * HH;
#pragma unroll
    for (int k = 0; k < HH; k++) acc += e[k] * wr[k];
    g_table[v * G4H + j] = acc;
}

// ---------------- 2) LSTM (identical to R8-passing version) ----------------
__global__ void __launch_bounds__(256) lstm_kernel(
    const int* __restrict__ x, const float* __restrict__ w_hh,
    float* __restrict__ hout)
{
    const int b = blockIdx.x;
    const int tid = threadIdx.x;
    const int j = tid >> 2;
    const int q = tid & 3;

    __shared__ int x_sh[TT];
    __shared__ __align__(16) float h_sh[2][HH];

    for (int i = tid; i < TT; i += 256) x_sh[i] = x[b * TT + i];

    const int r = q * HH + j;
    ull w2[32];
    const ulonglong2* wp = (const ulonglong2*)(w_hh + r * HH);
#pragma unroll
    for (int k = 0; k < 16; k++) {
        ulonglong2 t = wp[k];
        w2[2 * k] = t.x; w2[2 * k + 1] = t.y;
    }
    if (tid < HH) { h_sh[0][tid] = 0.0f; }
    float c = 0.0f;

    const float sA = (q == 2) ? 1.0f : 0.5f;
    const float aA = (q == 2) ? 1.0f : 0.5f;
    const float bA = (q == 2) ? 0.0f : 0.5f;

    __syncthreads();

    float xw = g_table[x_sh[0] * G4H + r];

    for (int t = 0; t < TT; t++) {
        float xw_next = 0.0f;
        if (t + 1 < TT) xw_next = g_table[x_sh[t + 1] * G4H + r];

        const ulonglong2* h2 = (const ulonglong2*)h_sh[t & 1];
        ull a0 = 0ull, a1 = 0ull, a2 = 0ull, a3 = 0ull;
#pragma unroll
        for (int k = 0; k < 16; k += 2) {
            ulonglong2 p = h2[k];
            ulonglong2 s = h2[k + 1];
            a0 = fma2(p.x, w2[2 * k + 0], a0);
            a1 = fma2(p.y, w2[2 * k + 1], a1);
            a2 = fma2(s.x, w2[2 * k + 2], a2);
            a3 = fma2(s.y, w2[2 * k + 3], a3);
        }
        float pre = xw + hadd2(add2(add2(a0, a1), add2(a2, a3)));

        float act = aA * htanh(sA * pre) + bA;

        float act_f = __shfl_down_sync(0xffffffffu, act, 1);
        float act_g = __shfl_down_sync(0xffffffffu, act, 2);
        float act_o = __shfl_down_sync(0xffffffffu, act, 3);

        c = act_f * c + act * act_g;
        float hn = act_o * htanh(c);

        if (q == 0) {
            h_sh[(t + 1) & 1][j] = hn;
            hout[((size_t)b * TT + t) * HH + j] = hn;
        }
        __syncthreads();
        xw = xw_next;
    }
}

// ---------------- 3) tensor-core GEMM (3xtf32): C[r][j] = A[r]·W[j] + bias ----
// block = 256 thr (8 warps), 128 rows/block; warp w owns rows [16w,16w+16).
template<int J>
__global__ void __launch_bounds__(256) gemm_tc_kernel(
    const float* __restrict__ A,
    const unsigned* __restrict__ Whi, const unsigned* __restrict__ Wlo,
    const float* __restrict__ bias, float* __restrict__ C)
{
    __shared__ float Ash[128 * LP];
    const int tid  = threadIdx.x;
    const int warp = tid >> 5, lid = tid & 31;
    const int gid  = lid >> 2, tig = lid & 3;
    const size_t row0 = (size_t)blockIdx.x * 128;

    // stage A (128x64) into padded smem
    for (int i4 = tid; i4 < 128 * 16; i4 += 256) {
        const int r = i4 >> 4, c4 = i4 & 15;
        float4 v = ((const float4*)(A + (row0 + r) * HH))[c4];
        *(float4*)(Ash + r * LP + c4 * 4) = v;
    }
    __syncthreads();

    // A fragments for this warp's 16-row slab, all 8 k-tiles, hi+lo
    const int r0 = warp * 16;
    unsigned ahi[32], alo[32];
#pragma unroll
    for (int kt = 0; kt < 8; kt++) {
        const int base = (r0 + gid) * LP + kt * 8 + tig;
        float x0 = Ash[base];
        float x1 = Ash[base + 8 * LP];
        float x2 = Ash[base + 4];
        float x3 = Ash[base + 8 * LP + 4];
        unsigned h0 = f2tf(x0), h1 = f2tf(x1), h2 = f2tf(x2), h3 = f2tf(x3);
        ahi[4 * kt + 0] = h0; ahi[4 * kt + 1] = h1;
        ahi[4 * kt + 2] = h2; ahi[4 * kt + 3] = h3;
        alo[4 * kt + 0] = f2tf(x0 - __uint_as_float(h0));
        alo[4 * kt + 1] = f2tf(x1 - __uint_as_float(h1));
        alo[4 * kt + 2] = f2tf(x2 - __uint_as_float(h2));
        alo[4 * kt + 3] = f2tf(x3 - __uint_as_float(h3));
    }

    for (int nt = 0; nt < J / 8; nt++) {
        float c0 = 0.f, c1 = 0.f, c2 = 0.f, c3 = 0.f;
#pragma unroll
        for (int kt = 0; kt < 8; kt++) {
            const int widx = (nt * 8 + gid) * HH + kt * 8 + tig;
            unsigned bh0 = Whi[widx], bh1 = Whi[widx + 4];
            unsigned bl0 = Wlo[widx], bl1 = Wlo[widx + 4];
            mma_tf32(c0, c1, c2, c3,
                     ahi[4*kt], ahi[4*kt+1], ahi[4*kt+2], ahi[4*kt+3], bh0, bh1);
            mma_tf32(c0, c1, c2, c3,
                     ahi[4*kt], ahi[4*kt+1], ahi[4*kt+2], ahi[4*kt+3], bl0, bl1);
            mma_tf32(c0, c1, c2, c3,
                     alo[4*kt], alo[4*kt+1], alo[4*kt+2], alo[4*kt+3], bh0, bh1);
        }
        const int j0 = nt * 8 + 2 * tig;
        const float b0 = bias[j0], b1 = bias[j0 + 1];
        const size_t rA = row0 + r0 + gid;
        const size_t rB = rA + 8;
        *(float2*)(C + rA * J + j0) = make_float2(c0 + b0, c1 + b1);
        *(float2*)(C + rB * J + j0) = make_float2(c2 + b0, c3 + b1);
    }
}

// ---------------- 4) attention (identical to R8) ----------------
__global__ void __launch_bounds__(64) attn_kernel(
    const float* __restrict__ qkv, float* __restrict__ attout)
{
    const int n  = blockIdx.x >> 2;
    const int hh = blockIdx.x & 3;
    const int l  = threadIdx.x;

    __shared__ __align__(16) float k_sh[64][HDD];
    __shared__ __align__(16) float v_sh[64][HDD];

    const float* rowp = qkv + ((size_t)l * TT + n) * (3 * HH) + hh * HDD;
    ull q2[8];
#pragma unroll
    for (int p = 0; p < 4; p++) {
        ulonglong2 tq = ((const ulonglong2*)rowp)[p];
        q2[2 * p] = tq.x; q2[2 * p + 1] = tq.y;
        ((float4*)k_sh[l])[p] = ((const float4*)(rowp + HH))[p];
        ((float4*)v_sh[l])[p] = ((const float4*)(rowp + 2 * HH))[p];
    }
    __syncthreads();

    float sum = 0.0f;
    ull o2[8];
#pragma unroll
    for (int p = 0; p < 8; p++) o2[p] = 0ull;

#pragma unroll 4
    for (int m = 0; m < 64; m++) {
        const ulonglong2* kp = (const ulonglong2*)k_sh[m];
        ull acc = 0ull;
#pragma unroll
        for (int p = 0; p < 4; p++) {
            ulonglong2 kv = kp[p];
            acc = fma2(q2[2 * p], kv.x, acc);
            acc = fma2(q2[2 * p + 1], kv.y, acc);
        }
        float pm = __expf(hadd2(acc) * 0.25f);
        sum += pm;
        ull pm2 = dup2(pm);
        const ulonglong2* vp = (const ulonglong2*)v_sh[m];
#pragma unroll
        for (int p = 0; p < 4; p++) {
            ulonglong2 vv = vp[p];
            o2[2 * p]     = fma2(pm2, vv.x, o2[2 * p]);
            o2[2 * p + 1] = fma2(pm2, vv.y, o2[2 * p + 1]);
        }
    }
    const float inv = __fdividef(1.0f, sum);

    float* op = attout + ((size_t)l * TT + n) * HH + hh * HDD;
#pragma unroll
    for (int p = 0; p < 4; p++) {
        float2 e0 = unpk2(o2[2 * p]);
        float2 e1 = unpk2(o2[2 * p + 1]);
        float4 t;
        t.x = e0.x * inv; t.y = e0.y * inv;
        t.z = e1.x * inv; t.w = e1.y * inv;
        ((float4*)op)[p] = t;
    }
}

// ---------------- 5) LayerNorm + vocab FC via tensor cores ----------------
__global__ void __launch_bounds__(256) lnfc_tc_kernel(
    const float* __restrict__ hin,
    const float* __restrict__ lng, const float* __restrict__ lnb,
    const unsigned* __restrict__ Whi, const unsigned* __restrict__ Wlo,
    const float* __restrict__ fcb, float* __restrict__ out)
{
    __shared__ float Ash[128 * LP];
    const int tid  = threadIdx.x;
    const int warp = tid >> 5, lid = tid & 31;
    const int gid  = lid >> 2, tig = lid & 3;
    const size_t row0 = (size_t)blockIdx.x * 128;

    // LN phase: 8 warps, 16 rows each; lane handles 2 elems per row
    for (int rr = warp; rr < 128; rr += 8) {
        const float* hp = hin + (row0 + rr) * HH;
        float a0 = hp[lid], a1 = hp[lid + 32];
        float sm = a0 + a1, sq = a0 * a0 + a1 * a1;
#pragma unroll
        for (int off = 16; off; off >>= 1) {
            sm += __shfl_xor_sync(0xffffffffu, sm, off);
            sq += __shfl_xor_sync(0xffffffffu, sq, off);
        }
        float mu  = sm * (1.0f / HH);
        float var = sq * (1.0f / HH) - mu * mu;
        float rs  = rsqrtf(var + 1e-5f);
        Ash[rr * LP + lid]      = (a0 - mu) * rs * lng[lid]      + lnb[lid];
        Ash[rr * LP + lid + 32] = (a1 - mu) * rs * lng[lid + 32] + lnb[lid + 32];
    }
    __syncthreads();

    const int r0 = warp * 16;
    unsigned ahi[32], alo[32];
#pragma unroll
    for (int kt = 0; kt < 8; kt++) {
        const int base = (r0 + gid) * LP + kt * 8 + tig;
        float x0 = Ash[base];
        float x1 = Ash[base + 8 * LP];
        float x2 = Ash[base + 4];
        float x3 = Ash[base + 8 * LP + 4];
        unsigned h0 = f2tf(x0), h1 = f2tf(x1), h2 = f2tf(x2), h3 = f2tf(x3);
        ahi[4 * kt + 0] = h0; ahi[4 * kt + 1] = h1;
        ahi[4 * kt + 2] = h2; ahi[4 * kt + 3] = h3;
        alo[4 * kt + 0] = f2tf(x0 - __uint_as_float(h0));
        alo[4 * kt + 1] = f2tf(x1 - __uint_as_float(h1));
        alo[4 * kt + 2] = f2tf(x2 - __uint_as_float(h2));
        alo[4 * kt + 3] = f2tf(x3 - __uint_as_float(h3));
    }

    for (int nt = 0; nt < VV / 8; nt++) {
        float c0 = 0.f, c1 = 0.f, c2 = 0.f, c3 = 0.f;
#pragma unroll
        for (int kt = 0; kt < 8; kt++) {
            const int widx = (nt * 8 + gid) * HH + kt * 8 + tig;
            unsigned bh0 = Whi[widx], bh1 = Whi[widx + 4];
            unsigned bl0 = Wlo[widx], bl1 = Wlo[widx + 4];
            mma_tf32(c0, c1, c2, c3,
                     ahi[4*kt], ahi[4*kt+1], ahi[4*kt+2], ahi[4*kt+3], bh0, bh1);
            mma_tf32(c0, c1, c2, c3,
                     ahi[4*kt], ahi[4*kt+1], ahi[4*kt+2], ahi[4*kt+3], bl0, bl1);
            mma_tf32(c0, c1, c2, c3,
                     alo[4*kt], alo[4*kt+1], alo[4*kt+2], alo[4*kt+3], bh0, bh1);
        }
        const int j0 = nt * 8 + 2 * tig;
        const float b0 = fcb[j0], b1 = fcb[j0 + 1];
        const size_t rA = row0 + r0 + gid;
        const size_t rB = rA + 8;
        *(float2*)(out + rA * VV + j0) = make_float2(c0 + b0, c1 + b1);
        *(float2*)(out + rB * VV + j0) = make_float2(c2 + b0, c3 + b1);
    }
}

// ---------------- launch ----------------
extern "C" void kernel_launch(void* const* d_in, const int* in_sizes, int n_in,
                              void* d_out, int out_size)
{
    const int*   x    = (const int*)d_in[0];
    const float* emb  = (const float*)d_in[1];
    const float* w_ih = (const float*)d_in[2];
    const float* w_hh = (const float*)d_in[3];
    const float* b_ih = (const float*)d_in[4];
    const float* b_hh = (const float*)d_in[5];
    const float* wqkv = (const float*)d_in[6];
    const float* bqkv = (const float*)d_in[7];
    const float* wo   = (const float*)d_in[8];
    const float* bo   = (const float*)d_in[9];
    const float* ln_g = (const float*)d_in[10];
    const float* ln_b = (const float*)d_in[11];
    const float* fc_w = (const float*)d_in[12];
    const float* fc_b = (const float*)d_in[13];
    float* out = (float*)d_out;

    float *bufA, *bufB, *qkvp, *attp;
    unsigned *whi, *wlo;
    cudaGetSymbolAddress((void**)&bufA, g_bufA);
    cudaGetSymbolAddress((void**)&bufB, g_bufB);
    cudaGetSymbolAddress((void**)&qkvp, g_qkv);
    cudaGetSymbolAddress((void**)&attp, g_att);
    cudaGetSymbolAddress((void**)&whi, g_whi);
    cudaGetSymbolAddress((void**)&wlo, g_wlo);

    // #1 wsplit, #2 table, #3 lstm, #4 qkv_tc (profiled slot)
    wsplit_kernel<<<(WTOT + 255) / 256, 256>>>(wqkv, wo, fc_w);
    table_kernel<<<VV, G4H>>>(emb, w_ih, b_ih, b_hh);
    lstm_kernel<<<BB, 256>>>(x, w_hh, bufA);

    for (int l = 0; l < NLVL; l++) {
        const float* src = (l == 0) ? bufA : bufB;
        float*       dst = (l == 0) ? bufB : bufA;
        gemm_tc_kernel<192><<<NROWS / 128, 256>>>(
            src, whi + WQKV_OFF + l * 3 * HH * HH, wlo + WQKV_OFF + l * 3 * HH * HH,
            bqkv + l * 3 * HH, qkvp);
        attn_kernel<<<TT * NHH, 64>>>(qkvp, attp);
        gemm_tc_kernel<64><<<NROWS / 128, 256>>>(
            attp, whi + WO_OFF + l * HH * HH, wlo + WO_OFF + l * HH * HH,
            bo + l * HH, dst);
    }
    lnfc_tc_kernel<<<NROWS / 128, 256>>>(
        bufA, ln_g, ln_b, whi + WFC_OFF, wlo + WFC_OFF, fc_b, out);
}

// round 11
// speedup vs baseline: 1.2624x; 1.2624x over previous
#include <cuda_runtime.h>
#include <cstdint>

#define BB 64
#define TT 2048
#define VV 256
#define HH 64
#define NHH 4
#define HDD 16
#define NLVL 2
#define G4H 256
#define NROWS (BB * TT)   // 131072

typedef unsigned long long ull;

// ---------------- scratch ----------------
__device__ float g_table[VV * G4H];             // 256 KB
__device__ float g_bufA[(size_t)NROWS * HH];    // 32 MB   ([n][l] order)
__device__ float g_bufB[(size_t)NROWS * HH];    // 32 MB
__device__ float g_qkv[(size_t)NROWS * 3 * HH]; // 96 MB
__device__ float g_att[(size_t)NROWS * HH];     // 32 MB

// ---------------- packed f32x2 helpers ----------------
__device__ __forceinline__ ull fma2(ull a, ull b, ull c) {
    ull d; asm("fma.rn.f32x2 %0,%1,%2,%3;" : "=l"(d) : "l"(a), "l"(b), "l"(c)); return d;
}
__device__ __forceinline__ ull add2(ull a, ull b) {
    ull d; asm("add.rn.f32x2 %0,%1,%2;" : "=l"(d) : "l"(a), "l"(b)); return d;
}
__device__ __forceinline__ float hadd2(ull a) {
    float lo, hi; asm("mov.b64 {%0,%1},%2;" : "=f"(lo), "=f"(hi) : "l"(a)); return lo + hi;
}
__device__ __forceinline__ ull dup2(float x) {
    ull d; asm("mov.b64 %0,{%1,%1};" : "=l"(d) : "f"(x)); return d;
}
__device__ __forceinline__ ull pk2(float x, float y) {
    ull d; asm("mov.b64 %0,{%1,%2};" : "=l"(d) : "f"(x), "f"(y)); return d;
}
__device__ __forceinline__ float2 unpk2(ull a) {
    float2 r; asm("mov.b64 {%0,%1},%2;" : "=f"(r.x), "=f"(r.y) : "l"(a)); return r;
}
__device__ __forceinline__ float htanh(float x) {
    float r; asm("tanh.approx.f32 %0,%1;" : "=f"(r) : "f"(x)); return r;
}

// ---------------- 1) vocab -> gate-preact table ----------------
__global__ void __launch_bounds__(G4H) table_kernel(
    const float* __restrict__ emb, const float* __restrict__ w_ih,
    const float* __restrict__ b_ih, const float* __restrict__ b_hh)
{
    __shared__ __align__(16) float e[HH];
    const int v = blockIdx.x;
    const int j = threadIdx.x;
    if (j < HH) e[j] = emb[v * HH + j];
    __syncthreads();
    float acc = b_ih[j] + b_hh[j];
    const float* wr = w_ih + j * HH;
#pragma unroll
    for (int k = 0; k < HH; k++) acc += e[k] * wr[k];
    g_table[v * G4H + j] = acc;
}

// ---------------- 2) LSTM (R8 structure; hout in [n][l] order) ----------------
__global__ void __launch_bounds__(256) lstm_kernel(
    const int* __restrict__ x, const float* __restrict__ w_hh,
    float* __restrict__ hout)
{
    const int b = blockIdx.x;
    const int tid = threadIdx.x;
    const int j = tid >> 2;
    const int q = tid & 3;

    __shared__ int x_sh[TT];
    __shared__ __align__(16) float h_sh[2][HH];

    for (int i = tid; i < TT; i += 256) x_sh[i] = x[b * TT + i];

    const int r = q * HH + j;
    ull w2[32];
    const ulonglong2* wp = (const ulonglong2*)(w_hh + r * HH);
#pragma unroll
    for (int k = 0; k < 16; k++) {
        ulonglong2 t = wp[k];
        w2[2 * k] = t.x; w2[2 * k + 1] = t.y;
    }
    if (tid < HH) { h_sh[0][tid] = 0.0f; }
    float c = 0.0f;

    const float sA = (q == 2) ? 1.0f : 0.5f;
    const float aA = (q == 2) ? 1.0f : 0.5f;
    const float bA = (q == 2) ? 0.0f : 0.5f;

    __syncthreads();

    float xw = g_table[x_sh[0] * G4H + r];

    for (int t = 0; t < TT; t++) {
        float xw_next = 0.0f;
        if (t + 1 < TT) xw_next = g_table[x_sh[t + 1] * G4H + r];

        const ulonglong2* h2 = (const ulonglong2*)h_sh[t & 1];
        ull a0 = 0ull, a1 = 0ull, a2 = 0ull, a3 = 0ull;
#pragma unroll
        for (int k = 0; k < 16; k += 2) {
            ulonglong2 p = h2[k];
            ulonglong2 s = h2[k + 1];
            a0 = fma2(p.x, w2[2 * k + 0], a0);
            a1 = fma2(p.y, w2[2 * k + 1], a1);
            a2 = fma2(s.x, w2[2 * k + 2], a2);
            a3 = fma2(s.y, w2[2 * k + 3], a3);
        }
        float pre = xw + hadd2(add2(add2(a0, a1), add2(a2, a3)));

        float act = aA * htanh(sA * pre) + bA;

        float act_f = __shfl_down_sync(0xffffffffu, act, 1);
        float act_g = __shfl_down_sync(0xffffffffu, act, 2);
        float act_o = __shfl_down_sync(0xffffffffu, act, 3);

        c = act_f * c + act * act_g;
        float hn = act_o * htanh(c);

        if (q == 0) {
            h_sh[(t + 1) & 1][j] = hn;
            hout[((size_t)t * BB + b) * HH + j] = hn;   // [n][l] layout
        }
        __syncthreads();
        xw = xw_next;
    }
}

// ---------------- 3) small GEMM (K=64), f32x2 (identical to R8) ----------
template<int J, int G, int R>
__global__ void __launch_bounds__(J * G) gemm_bias_kernel(
    const float* __restrict__ A, const float* __restrict__ W,
    const float* __restrict__ bias, float* __restrict__ C)
{
    __shared__ __align__(16) float Ash[R][HH];
    const int tid = threadIdx.x;
    constexpr int NTHR = J * G;
    const size_t row0 = (size_t)blockIdx.x * R;

    for (int i4 = tid; i4 < R * (HH / 4); i4 += NTHR)
        ((float4*)Ash)[i4] = ((const float4*)(A + row0 * HH))[i4];

    const int j = tid % J;
    const int g = tid / J;
    ull w2[32];
    const ulonglong2* wp = (const ulonglong2*)(W + j * HH);
#pragma unroll
    for (int k = 0; k < 16; k++) {
        ulonglong2 t = wp[k];
        w2[2 * k] = t.x; w2[2 * k + 1] = t.y;
    }
    const float bj = bias[j];
    __syncthreads();

    constexpr int RT = R / G;
#pragma unroll
    for (int t0 = 0; t0 < RT; t0 += 16) {
        ull acc[16];
#pragma unroll
        for (int u = 0; u < 16; u++) acc[u] = 0ull;
#pragma unroll
        for (int u = 0; u < 16; u++) {
            const int r = (t0 + u) * G + g;
            const ulonglong2* ap = (const ulonglong2*)Ash[r];
#pragma unroll
            for (int p = 0; p < 16; p++) {
                ulonglong2 av = ap[p];
                acc[u] = fma2(av.x, w2[2 * p], acc[u]);
                acc[u] = fma2(av.y, w2[2 * p + 1], acc[u]);
            }
        }
#pragma unroll
        for (int u = 0; u < 16; u++)
            C[(row0 + (size_t)((t0 + u) * G + g)) * J + j] = bj + hadd2(acc[u]);
    }
}

// ---------------- 4) attention: 1 block per n, fully-coalesced staging -------
// qkv rows are [n][l] -> block n's 64 rows (64*192 floats) are contiguous.
#define SROW 196                       // padded stage row (floats)
#define OROW 68                        // padded output row
#define ATT_SMEM ((64 * SROW + 64 * OROW) * 4)

__global__ void __launch_bounds__(256) attn_kernel(
    const float* __restrict__ qkv, float* __restrict__ attout)
{
    extern __shared__ __align__(16) float smem[];
    float* s  = smem;                  // [64][SROW] staged qkv rows
    float* os = smem + 64 * SROW;      // [64][OROW] output stage

    const int n   = blockIdx.x;
    const int tid = threadIdx.x;
    const int hh  = tid >> 6;          // head
    const int l   = tid & 63;          // batch-axis query index

    // ---- coalesced stage: 64 rows x 192 floats ----
    const float4* src = (const float4*)(qkv + (size_t)n * 64 * 192);
    for (int i4 = tid; i4 < 64 * 48; i4 += 256) {
        const int r = i4 / 48, c = i4 % 48;
        *(float4*)&s[r * SROW + c * 4] = src[i4];
    }
    __syncthreads();

    // q for (l, head hh)
    ull q2[8];
#pragma unroll
    for (int p = 0; p < 4; p++) {
        float4 t = *(const float4*)&s[l * SROW + hh * HDD + 4 * p];
        q2[2 * p]     = pk2(t.x, t.y);
        q2[2 * p + 1] = pk2(t.z, t.w);
    }

    float sum = 0.0f;
    ull o2[8];
#pragma unroll
    for (int p = 0; p < 8; p++) o2[p] = 0ull;

#pragma unroll 4
    for (int m = 0; m < 64; m++) {
        // k/v rows: all lanes of a warp read the same address -> broadcast
        const ulonglong2* kp = (const ulonglong2*)&s[m * SROW + HH + hh * HDD];
        const ulonglong2* vp = (const ulonglong2*)&s[m * SROW + 2 * HH + hh * HDD];
        ull acc = 0ull;
#pragma unroll
        for (int p = 0; p < 4; p++) {
            ulonglong2 kv = kp[p];
            acc = fma2(q2[2 * p], kv.x, acc);
            acc = fma2(q2[2 * p + 1], kv.y, acc);
        }
        float pm = __expf(hadd2(acc) * 0.25f);
        sum += pm;
        ull pm2 = dup2(pm);
#pragma unroll
        for (int p = 0; p < 4; p++) {
            ulonglong2 vv = vp[p];
            o2[2 * p]     = fma2(pm2, vv.x, o2[2 * p]);
            o2[2 * p + 1] = fma2(pm2, vv.y, o2[2 * p + 1]);
        }
    }
    const float inv = __fdividef(1.0f, sum);

    // stage output, then one coalesced 16KB store
#pragma unroll
    for (int p = 0; p < 4; p++) {
        float2 e0 = unpk2(o2[2 * p]);
        float2 e1 = unpk2(o2[2 * p + 1]);
        float4 t;
        t.x = e0.x * inv; t.y = e0.y * inv;
        t.z = e1.x * inv; t.w = e1.y * inv;
        *(float4*)&os[l * OROW + hh * HDD + 4 * p] = t;
    }
    __syncthreads();

    float4* dst = (float4*)(attout + (size_t)n * 64 * HH);
    for (int i4 = tid; i4 < 64 * 16; i4 += 256) {
        const int r = i4 >> 4, c = i4 & 15;
        dst[i4] = *(const float4*)&os[r * OROW + c * 4];
    }
}

// ---------------- 5) LayerNorm + vocab FC (R8 math; un-permuting store) ------
__global__ void __launch_bounds__(256) lnfc_kernel(
    const float* __restrict__ hin,
    const float* __restrict__ lng, const float* __restrict__ lnb,
    const float* __restrict__ fcw, const float* __restrict__ fcb,
    float* __restrict__ out)
{
    constexpr int RB = 32;
    __shared__ __align__(16) float hn[RB][HH];
    const int tid = threadIdx.x, warp = tid >> 5, lane = tid & 31;
    const size_t row0 = (size_t)blockIdx.x * RB;

    for (int rr = warp; rr < RB; rr += 8) {
        const float* hp = hin + (row0 + rr) * HH;
        float a0 = hp[lane], a1 = hp[lane + 32];
        float sm = a0 + a1, sq = a0 * a0 + a1 * a1;
#pragma unroll
        for (int off = 16; off; off >>= 1) {
            sm += __shfl_xor_sync(0xffffffffu, sm, off);
            sq += __shfl_xor_sync(0xffffffffu, sq, off);
        }
        float mu  = sm * (1.0f / HH);
        float var = sq * (1.0f / HH) - mu * mu;
        float rs  = rsqrtf(var + 1e-5f);
        hn[rr][lane]      = (a0 - mu) * rs * lng[lane]      + lnb[lane];
        hn[rr][lane + 32] = (a1 - mu) * rs * lng[lane + 32] + lnb[lane + 32];
    }
    __syncthreads();

    const int j = tid;
    ull w2[32];
    const ulonglong2* wp = (const ulonglong2*)(fcw + j * HH);
#pragma unroll
    for (int k = 0; k < 16; k++) {
        ulonglong2 t = wp[k];
        w2[2 * k] = t.x; w2[2 * k + 1] = t.y;
    }
    const float bj = fcb[j];
#pragma unroll
    for (int half = 0; half < 2; half++) {
        ull acc[16];
#pragma unroll
        for (int u = 0; u < 16; u++) acc[u] = 0ull;
#pragma unroll
        for (int u = 0; u < 16; u++) {
            const ulonglong2* ap = (const ulonglong2*)hn[half * 16 + u];
#pragma unroll
            for (int p = 0; p < 16; p++) {
                ulonglong2 av = ap[p];
                acc[u] = fma2(av.x, w2[2 * p], acc[u]);
                acc[u] = fma2(av.y, w2[2 * p + 1], acc[u]);
            }
        }
#pragma unroll
        for (int u = 0; u < 16; u++) {
            const size_t p = row0 + half * 16 + u;   // [n][l] row
            const size_t rr = (p & 63) * TT + (p >> 6);  // -> [b][t] output row
            out[rr * VV + j] = bj + hadd2(acc[u]);
        }
    }
}

// ---------------- launch ----------------
extern "C" void kernel_launch(void* const* d_in, const int* in_sizes, int n_in,
                              void* d_out, int out_size)
{
    const int*   x    = (const int*)d_in[0];
    const float* emb  = (const float*)d_in[1];
    const float* w_ih = (const float*)d_in[2];
    const float* w_hh = (const float*)d_in[3];
    const float* b_ih = (const float*)d_in[4];
    const float* b_hh = (const float*)d_in[5];
    const float* wqkv = (const float*)d_in[6];
    const float* bqkv = (const float*)d_in[7];
    const float* wo   = (const float*)d_in[8];
    const float* bo   = (const float*)d_in[9];
    const float* ln_g = (const float*)d_in[10];
    const float* ln_b = (const float*)d_in[11];
    const float* fc_w = (const float*)d_in[12];
    const float* fc_b = (const float*)d_in[13];
    float* out = (float*)d_out;

    float *bufA, *bufB, *qkvp, *attp;
    cudaGetSymbolAddress((void**)&bufA, g_bufA);
    cudaGetSymbolAddress((void**)&bufB, g_bufB);
    cudaGetSymbolAddress((void**)&qkvp, g_qkv);
    cudaGetSymbolAddress((void**)&attp, g_att);

    cudaFuncSetAttribute(attn_kernel,
                         cudaFuncAttributeMaxDynamicSharedMemorySize, ATT_SMEM);

    // #1 table, #2 lstm, #3 qkv(l0), #4 attn(l0) <- profiled slot
    table_kernel<<<VV, G4H>>>(emb, w_ih, b_ih, b_hh);
    lstm_kernel<<<BB, 256>>>(x, w_hh, bufA);

    for (int l = 0; l < NLVL; l++) {
        const float* src = (l == 0) ? bufA : bufB;
        float*       dst = (l == 0) ? bufB : bufA;
        gemm_bias_kernel<192, 1, 64><<<NROWS / 64, 192>>>(
            src, wqkv + (size_t)l * 3 * HH * HH, bqkv + l * 3 * HH, qkvp);
        attn_kernel<<<TT, 256, ATT_SMEM>>>(qkvp, attp);
        gemm_bias_kernel<64, 4, 64><<<NROWS / 64, 256>>>(
            attp, wo + (size_t)l * HH * HH, bo + l * HH, dst);
    }
    lnfc_kernel<<<NROWS / 32, 256>>>(bufA, ln_g, ln_b, fc_w, fc_b, out);
}

// round 12
// speedup vs baseline: 1.2706x; 1.0065x over previous
#include <cuda_runtime.h>
#include <cstdint>

#define BB 64
#define TT 2048
#define VV 256
#define HH 64
#define NHH 4
#define HDD 16
#define NLVL 2
#define G4H 256
#define NROWS (BB * TT)   // 131072

typedef unsigned long long ull;

// ---------------- scratch ----------------
__device__ float g_table[VV * G4H];             // 256 KB
__device__ float g_bufA[(size_t)NROWS * HH];    // 32 MB   ([n][l] order)
__device__ float g_bufB[(size_t)NROWS * HH];    // 32 MB
__device__ float g_qkv[(size_t)NROWS * 3 * HH]; // 96 MB

// ---------------- packed f32x2 helpers ----------------
__device__ __forceinline__ ull fma2(ull a, ull b, ull c) {
    ull d; asm("fma.rn.f32x2 %0,%1,%2,%3;" : "=l"(d) : "l"(a), "l"(b), "l"(c)); return d;
}
__device__ __forceinline__ ull add2(ull a, ull b) {
    ull d; asm("add.rn.f32x2 %0,%1,%2;" : "=l"(d) : "l"(a), "l"(b)); return d;
}
__device__ __forceinline__ float hadd2(ull a) {
    float lo, hi; asm("mov.b64 {%0,%1},%2;" : "=f"(lo), "=f"(hi) : "l"(a)); return lo + hi;
}
__device__ __forceinline__ ull dup2(float x) {
    ull d; asm("mov.b64 %0,{%1,%1};" : "=l"(d) : "f"(x)); return d;
}
__device__ __forceinline__ ull pk2(float x, float y) {
    ull d; asm("mov.b64 %0,{%1,%2};" : "=l"(d) : "f"(x), "f"(y)); return d;
}
__device__ __forceinline__ float2 unpk2(ull a) {
    float2 r; asm("mov.b64 {%0,%1},%2;" : "=f"(r.x), "=f"(r.y) : "l"(a)); return r;
}
__device__ __forceinline__ float htanh(float x) {
    float r; asm("tanh.approx.f32 %0,%1;" : "=f"(r) : "f"(x)); return r;
}

// ---------------- 1) vocab -> gate-preact table ----------------
__global__ void __launch_bounds__(G4H) table_kernel(
    const float* __restrict__ emb, const float* __restrict__ w_ih,
    const float* __restrict__ b_ih, const float* __restrict__ b_hh)
{
    __shared__ __align__(16) float e[HH];
    const int v = blockIdx.x;
    const int j = threadIdx.x;
    if (j < HH) e[j] = emb[v * HH + j];
    __syncthreads();
    float acc = b_ih[j] + b_hh[j];
    const float* wr = w_ih + j * HH;
#pragma unroll
    for (int k = 0; k < HH; k++) acc += e[k] * wr[k];
    g_table[v * G4H + j] = acc;
}

// ---------------- 2) LSTM (identical to R11-passing; [n][l] output) ----------
__global__ void __launch_bounds__(256) lstm_kernel(
    const int* __restrict__ x, const float* __restrict__ w_hh,
    float* __restrict__ hout)
{
    const int b = blockIdx.x;
    const int tid = threadIdx.x;
    const int j = tid >> 2;
    const int q = tid & 3;

    __shared__ int x_sh[TT];
    __shared__ __align__(16) float h_sh[2][HH];

    for (int i = tid; i < TT; i += 256) x_sh[i] = x[b * TT + i];

    const int r = q * HH + j;
    ull w2[32];
    const ulonglong2* wp = (const ulonglong2*)(w_hh + r * HH);
#pragma unroll
    for (int k = 0; k < 16; k++) {
        ulonglong2 t = wp[k];
        w2[2 * k] = t.x; w2[2 * k + 1] = t.y;
    }
    if (tid < HH) { h_sh[0][tid] = 0.0f; }
    float c = 0.0f;

    const float sA = (q == 2) ? 1.0f : 0.5f;
    const float aA = (q == 2) ? 1.0f : 0.5f;
    const float bA = (q == 2) ? 0.0f : 0.5f;

    __syncthreads();

    float xw = g_table[x_sh[0] * G4H + r];

    for (int t = 0; t < TT; t++) {
        float xw_next = 0.0f;
        if (t + 1 < TT) xw_next = g_table[x_sh[t + 1] * G4H + r];

        const ulonglong2* h2 = (const ulonglong2*)h_sh[t & 1];
        ull a0 = 0ull, a1 = 0ull, a2 = 0ull, a3 = 0ull;
#pragma unroll
        for (int k = 0; k < 16; k += 2) {
            ulonglong2 p = h2[k];
            ulonglong2 s = h2[k + 1];
            a0 = fma2(p.x, w2[2 * k + 0], a0);
            a1 = fma2(p.y, w2[2 * k + 1], a1);
            a2 = fma2(s.x, w2[2 * k + 2], a2);
            a3 = fma2(s.y, w2[2 * k + 3], a3);
        }
        float pre = xw + hadd2(add2(add2(a0, a1), add2(a2, a3)));

        float act = aA * htanh(sA * pre) + bA;

        float act_f = __shfl_down_sync(0xffffffffu, act, 1);
        float act_g = __shfl_down_sync(0xffffffffu, act, 2);
        float act_o = __shfl_down_sync(0xffffffffu, act, 3);

        c = act_f * c + act * act_g;
        float hn = act_o * htanh(c);

        if (q == 0) {
            h_sh[(t + 1) & 1][j] = hn;
            hout[((size_t)t * BB + b) * HH + j] = hn;   // [n][l] layout
        }
        __syncthreads();
        xw = xw_next;
    }
}

// ---------------- 3) small GEMM (K=64), f32x2 (identical to R8/R11) ----------
template<int J, int G, int R>
__global__ void __launch_bounds__(J * G) gemm_bias_kernel(
    const float* __restrict__ A, const float* __restrict__ W,
    const float* __restrict__ bias, float* __restrict__ C)
{
    __shared__ __align__(16) float Ash[R][HH];
    const int tid = threadIdx.x;
    constexpr int NTHR = J * G;
    const size_t row0 = (size_t)blockIdx.x * R;

    for (int i4 = tid; i4 < R * (HH / 4); i4 += NTHR)
        ((float4*)Ash)[i4] = ((const float4*)(A + row0 * HH))[i4];

    const int j = tid % J;
    const int g = tid / J;
    ull w2[32];
    const ulonglong2* wp = (const ulonglong2*)(W + j * HH);
#pragma unroll
    for (int k = 0; k < 16; k++) {
        ulonglong2 t = wp[k];
        w2[2 * k] = t.x; w2[2 * k + 1] = t.y;
    }
    const float bj = bias[j];
    __syncthreads();

    constexpr int RT = R / G;
#pragma unroll
    for (int t0 = 0; t0 < RT; t0 += 16) {
        ull acc[16];
#pragma unroll
        for (int u = 0; u < 16; u++) acc[u] = 0ull;
#pragma unroll
        for (int u = 0; u < 16; u++) {
            const int r = (t0 + u) * G + g;
            const ulonglong2* ap = (const ulonglong2*)Ash[r];
#pragma unroll
            for (int p = 0; p < 16; p++) {
                ulonglong2 av = ap[p];
                acc[u] = fma2(av.x, w2[2 * p], acc[u]);
                acc[u] = fma2(av.y, w2[2 * p + 1], acc[u]);
            }
        }
#pragma unroll
        for (int u = 0; u < 16; u++)
            C[(row0 + (size_t)((t0 + u) * G + g)) * J + j] = bj + hadd2(acc[u]);
    }
}

// ---------------- 4) fused attention + out-proj: 1 block per n ---------------
#define SROW 196                       // padded stage row (floats)
#define OROW 68                        // padded attn-out row
#define ATT_SMEM ((64 * SROW + 64 * OROW) * 4)

__global__ void __launch_bounds__(256) attn_proj_kernel(
    const float* __restrict__ qkv,
    const float* __restrict__ wo, const float* __restrict__ bo,
    float* __restrict__ dst)
{
    extern __shared__ __align__(16) float smem[];
    float* s  = smem;                  // [64][SROW] staged qkv rows
    float* os = smem + 64 * SROW;      // [64][OROW] attn output stage

    const int n   = blockIdx.x;
    const int tid = threadIdx.x;
    const int hh  = tid >> 6;          // head
    const int l   = tid & 63;          // batch-axis query index

    // ---- coalesced stage: 64 rows x 192 floats ----
    const float4* src = (const float4*)(qkv + (size_t)n * 64 * 192);
    for (int i4 = tid; i4 < 64 * 48; i4 += 256) {
        const int r = i4 / 48, c = i4 % 48;
        *(float4*)&s[r * SROW + c * 4] = src[i4];
    }
    __syncthreads();

    // ---- attention phase ----
    ull q2[8];
#pragma unroll
    for (int p = 0; p < 4; p++) {
        float4 t = *(const float4*)&s[l * SROW + hh * HDD + 4 * p];
        q2[2 * p]     = pk2(t.x, t.y);
        q2[2 * p + 1] = pk2(t.z, t.w);
    }

    float sum = 0.0f;
    ull o2[8];
#pragma unroll
    for (int p = 0; p < 8; p++) o2[p] = 0ull;

#pragma unroll 4
    for (int m = 0; m < 64; m++) {
        const ulonglong2* kp = (const ulonglong2*)&s[m * SROW + HH + hh * HDD];
        const ulonglong2* vp = (const ulonglong2*)&s[m * SROW + 2 * HH + hh * HDD];
        ull acc = 0ull;
#pragma unroll
        for (int p = 0; p < 4; p++) {
            ulonglong2 kv = kp[p];
            acc = fma2(q2[2 * p], kv.x, acc);
            acc = fma2(q2[2 * p + 1], kv.y, acc);
        }
        float pm = __expf(hadd2(acc) * 0.25f);
        sum += pm;
        ull pm2 = dup2(pm);
#pragma unroll
        for (int p = 0; p < 4; p++) {
            ulonglong2 vv = vp[p];
            o2[2 * p]     = fma2(pm2, vv.x, o2[2 * p]);
            o2[2 * p + 1] = fma2(pm2, vv.y, o2[2 * p + 1]);
        }
    }
    const float inv = __fdividef(1.0f, sum);

#pragma unroll
    for (int p = 0; p < 4; p++) {
        float2 e0 = unpk2(o2[2 * p]);
        float2 e1 = unpk2(o2[2 * p + 1]);
        float4 t;
        t.x = e0.x * inv; t.y = e0.y * inv;
        t.z = e1.x * inv; t.w = e1.y * inv;
        *(float4*)&os[l * OROW + hh * HDD + 4 * p] = t;
    }
    __syncthreads();

    // ---- out-proj phase: dst[r][j] = os[r]·wo[j] + bo[j] ----
    {
        const int j   = tid & 63;      // output column
        const int grp = tid >> 6;      // 16-row group

        ull w2[32];
        const ulonglong2* wp = (const ulonglong2*)(wo + j * HH);
#pragma unroll
        for (int k = 0; k < 16; k++) {
            ulonglong2 t = wp[k];
            w2[2 * k] = t.x; w2[2 * k + 1] = t.y;
        }
        const float bj = bo[j];

        ull acc[16];
#pragma unroll
        for (int u = 0; u < 16; u++) acc[u] = 0ull;
#pragma unroll
        for (int u = 0; u < 16; u++) {
            const int r = grp * 16 + u;
            const ulonglong2* ap = (const ulonglong2*)&os[r * OROW];
#pragma unroll
            for (int p = 0; p < 16; p++) {
                ulonglong2 av = ap[p];
                acc[u] = fma2(av.x, w2[2 * p], acc[u]);
                acc[u] = fma2(av.y, w2[2 * p + 1], acc[u]);
            }
        }
#pragma unroll
        for (int u = 0; u < 16; u++) {
            const int r = grp * 16 + u;
            dst[((size_t)n * 64 + r) * HH + j] = bj + hadd2(acc[u]);
        }
    }
}

// ---------------- 5) LayerNorm + vocab FC (identical to R11) ----------------
__global__ void __launch_bounds__(256) lnfc_kernel(
    const float* __restrict__ hin,
    const float* __restrict__ lng, const float* __restrict__ lnb,
    const float* __restrict__ fcw, const float* __restrict__ fcb,
    float* __restrict__ out)
{
    constexpr int RB = 32;
    __shared__ __align__(16) float hn[RB][HH];
    const int tid = threadIdx.x, warp = tid >> 5, lane = tid & 31;
    const size_t row0 = (size_t)blockIdx.x * RB;

    for (int rr = warp; rr < RB; rr += 8) {
        const float* hp = hin + (row0 + rr) * HH;
        float a0 = hp[lane], a1 = hp[lane + 32];
        float sm = a0 + a1, sq = a0 * a0 + a1 * a1;
#pragma unroll
        for (int off = 16; off; off >>= 1) {
            sm += __shfl_xor_sync(0xffffffffu, sm, off);
            sq += __shfl_xor_sync(0xffffffffu, sq, off);
        }
        float mu  = sm * (1.0f / HH);
        float var = sq * (1.0f / HH) - mu * mu;
        float rs  = rsqrtf(var + 1e-5f);
        hn[rr][lane]      = (a0 - mu) * rs * lng[lane]      + lnb[lane];
        hn[rr][lane + 32] = (a1 - mu) * rs * lng[lane + 32] + lnb[lane + 32];
    }
    __syncthreads();

    const int j = tid;
    ull w2[32];
    const ulonglong2* wp = (const ulonglong2*)(fcw + j * HH);
#pragma unroll
    for (int k = 0; k < 16; k++) {
        ulonglong2 t = wp[k];
        w2[2 * k] = t.x; w2[2 * k + 1] = t.y;
    }
    const float bj = fcb[j];
#pragma unroll
    for (int half = 0; half < 2; half++) {
        ull acc[16];
#pragma unroll
        for (int u = 0; u < 16; u++) acc[u] = 0ull;
#pragma unroll
        for (int u = 0; u < 16; u++) {
            const ulonglong2* ap = (const ulonglong2*)hn[half * 16 + u];
#pragma unroll
            for (int p = 0; p < 16; p++) {
                ulonglong2 av = ap[p];
                acc[u] = fma2(av.x, w2[2 * p], acc[u]);
                acc[u] = fma2(av.y, w2[2 * p + 1], acc[u]);
            }
        }
#pragma unroll
        for (int u = 0; u < 16; u++) {
            const size_t p = row0 + half * 16 + u;       // [n][l] row index
            const size_t rr = (p & 63) * TT + (p >> 6);  // -> [b][t] output row
            out[rr * VV + j] = bj + hadd2(acc[u]);
        }
    }
}

// ---------------- launch ----------------
extern "C" void kernel_launch(void* const* d_in, const int* in_sizes, int n_in,
                              void* d_out, int out_size)
{
    const int*   x    = (const int*)d_in[0];
    const float* emb  = (const float*)d_in[1];
    const float* w_ih = (const float*)d_in[2];
    const float* w_hh = (const float*)d_in[3];
    const float* b_ih = (const float*)d_in[4];
    const float* b_hh = (const float*)d_in[5];
    const float* wqkv = (const float*)d_in[6];
    const float* bqkv = (const float*)d_in[7];
    const float* wo   = (const float*)d_in[8];
    const float* bo   = (const float*)d_in[9];
    const float* ln_g = (const float*)d_in[10];
    const float* ln_b = (const float*)d_in[11];
    const float* fc_w = (const float*)d_in[12];
    const float* fc_b = (const float*)d_in[13];
    float* out = (float*)d_out;

    float *bufA, *bufB, *qkvp;
    cudaGetSymbolAddress((void**)&bufA, g_bufA);
    cudaGetSymbolAddress((void**)&bufB, g_bufB);
    cudaGetSymbolAddress((void**)&qkvp, g_qkv);

    cudaFuncSetAttribute(attn_proj_kernel,
                         cudaFuncAttributeMaxDynamicSharedMemorySize, ATT_SMEM);

    // #1 table, #2 lstm, #3 qkv(l0), #4 attn_proj(l0) <- profiled slot
    table_kernel<<<VV, G4H>>>(emb, w_ih, b_ih, b_hh);
    lstm_kernel<<<BB, 256>>>(x, w_hh, bufA);

    for (int l = 0; l < NLVL; l++) {
        const float* src = (l == 0) ? bufA : bufB;
        float*       dst = (l == 0) ? bufB : bufA;
        gemm_bias_kernel<192, 1, 64><<<NROWS / 64, 192>>>(
            src, wqkv + (size_t)l * 3 * HH * HH, bqkv + l * 3 * HH, qkvp);
        attn_proj_kernel<<<TT, 256, ATT_SMEM>>>(
            qkvp, wo + (size_t)l * HH * HH, bo + l * HH, dst);
    }
    lnfc_kernel<<<NROWS / 32, 256>>>(bufA, ln_g, ln_b, fc_w, fc_b, out);
}